// round 14
// baseline (speedup 1.0000x reference)
#include <cuda_runtime.h>
#include <cstdint>

typedef unsigned int u32;
typedef unsigned long long u64;

#define CS (65536L + 33554432L)   // per-component output stride (vn + sn)

// ---------------- helpers ---------------------------------------------------
__device__ __forceinline__ u32 smem_u32(const void* p) {
    u32 a;
    asm("{ .reg .u64 t; cvta.to.shared.u64 t, %1; cvt.u32.u64 %0, t; }" : "=r"(a) : "l"(p));
    return a;
}
__device__ __forceinline__ float to_tf32(float x) {
    float r;
    asm("cvt.rna.tf32.f32 %0, %1;" : "=f"(r) : "f"(x));
    return r;
}
__device__ __forceinline__ u32 lds32(u32 a) {
    u32 v;
    asm volatile("ld.shared.b32 %0, [%1];" : "=r"(v) : "r"(a));
    return v;
}
__device__ __forceinline__ void ldsm_x4(u32& r0, u32& r1, u32& r2, u32& r3, u32 addr) {
    asm volatile("ldmatrix.sync.aligned.m8n8.x4.shared.b16 {%0,%1,%2,%3}, [%4];"
                 : "=r"(r0), "=r"(r1), "=r"(r2), "=r"(r3) : "r"(addr));
}
__device__ __forceinline__ void mma16808(float* c, const u32* a, const u32* b) {
    asm volatile("mma.sync.aligned.m16n8k8.row.col.f32.tf32.tf32.f32 "
                 "{%0,%1,%2,%3}, {%4,%5,%6,%7}, {%8,%9}, {%0,%1,%2,%3};"
                 : "+f"(c[0]), "+f"(c[1]), "+f"(c[2]), "+f"(c[3])
                 : "r"(a[0]), "r"(a[1]), "r"(a[2]), "r"(a[3]), "r"(b[0]), "r"(b[1]));
}
__device__ __forceinline__ void cp16(u32 dst, const void* src) {
    asm volatile("cp.async.cg.shared.global [%0], [%1], 16;" :: "r"(dst), "l"(src));
}
// swizzled A image offset: row m, 512 B rows, 16 B chunks XOR (m & 7)
__device__ __forceinline__ u32 img_off(int m, int k) {
    return (u32)(m * 512 + (((k >> 2) ^ (m & 7)) << 4) + (k & 3) * 4);
}
// ---- f32x2 helpers ----
__device__ __forceinline__ u64 pack2(float lo, float hi) {
    u64 r;
    asm("mov.b64 %0, {%1, %2};" : "=l"(r) : "f"(lo), "f"(hi));
    return r;
}
__device__ __forceinline__ void unpack2(float& lo, float& hi, u64 v) {
    asm("mov.b64 {%0, %1}, %2;" : "=f"(lo), "=f"(hi) : "l"(v));
}
__device__ __forceinline__ u64 dup2(float w) {
    u64 r;
    asm("mov.b64 %0, {%1, %1};" : "=l"(r) : "f"(w));
    return r;
}
__device__ __forceinline__ void ffma2(u64& c, u64 a, u64 b) {
    asm("fma.rn.f32x2 %0, %1, %2, %0;" : "+l"(c) : "l"(a), "l"(b));
}
__device__ __forceinline__ u64 mul2(u64 a, u64 b) {
    u64 r;
    asm("mul.rn.f32x2 %0, %1, %2;" : "=l"(r) : "l"(a), "l"(b));
    return r;
}

// ---------------------------------------------------------------------------
// Single fused kernel: 148 persistent CTAs x 256 threads.
//  - CTAs 0-144 (sn): in-place Gauss-Jordan inversion of g (128 regs state,
//    no spills) with REAL __ldcg L2-prefetch of tiles t0+2..t0+9 interleaved
//    in 16 batches of 8 float4 (8-deep rotation, consumed one batch later),
//    so the GJ's DRAM-idle window streams ~74 MB chip-wide into L2.
//  - CTAs 145-147 (vn): A = g^T image.
//  - GEMM: tf32 mma.m16n8k8, A via ldmatrix, B streamed raw fp32 with
//    cp.async into native [k][n] swizzled layout, double-buffered tiles,
//    software-pipelined fragment loads.
// ---------------------------------------------------------------------------
#define SM_A 0
#define SM_B 65536                       // 2 stages x 64 KB
#define SMEM_TOTAL (65536 * 3)           // 192 KB dynamic

__global__ void __launch_bounds__(256, 1) main_kernel(
    const float* __restrict__ g0, const float* __restrict__ g1, const float* __restrict__ g2,
    const float* __restrict__ v0, const float* __restrict__ v1, const float* __restrict__ v2,
    const float* __restrict__ s0, const float* __restrict__ s1, const float* __restrict__ s2,
    float* __restrict__ out)
{
    __shared__ u64 rowk2[2][64];      // pivot row (packed pairs), ping-pong
    __shared__ float colk[2][128];    // pivot column, ping-pong
    extern __shared__ char smem[];
    const u32 sb = smem_u32(smem);
    const int tid = threadIdx.x, wid = tid >> 5, lane = tid & 31;
    const int bid = blockIdx.x;

    int comp, t0, t1;
    bool sn;
    if (bid < 145) {
        sn = true;
        comp = bid % 3;
        const int nC = (comp == 0) ? 49 : 48;
        const int ci = bid / 3;
        t0 = (ci * 2048) / nC;
        t1 = ((ci + 1) * 2048) / nC;
    } else {
        sn = false;
        comp = bid - 145;
        t0 = 0;
        t1 = 4;
    }
    const int nt = t1 - t0;
    const long Ms = sn ? 262144L : 512L;
    const float* Bsrc = sn ? (comp == 0 ? s0 : comp == 1 ? s1 : s2)
                           : (comp == 0 ? v0 : comp == 1 ? v1 : v2);
    const float* Gc = comp == 0 ? g0 : (comp == 1 ? g1 : g2);
    float* obase = out + (long)comp * CS + (sn ? 65536 : 0);

    // ---- cp.async pipeline: issue tile t into buffer p ----
    auto cpissue = [&](int t, int p) {
        const float* src = Bsrc + (long)t * 128;
        const u32 bdst = sb + SM_B + p * 65536;
#pragma unroll
        for (int q = 0; q < 16; q++) {
            const int e = q * 256 + tid;
            const int k = e >> 5, c = e & 31;
            cp16(bdst + k * 512 + ((c ^ ((k & 3) << 1)) << 4),
                 src + (long)k * Ms + c * 4);
        }
        asm volatile("cp.async.commit_group;" ::: "memory");
    };

    // get DRAM going before the A-image phase
    cpissue(t0, 0);
    if (nt > 1) cpissue(t0 + 1, 1);

    if (sn) {
        // ============== in-CTA IN-PLACE Gauss-Jordan inversion ==============
        // warp cg owns cols [cg*16, cg*16+16) as 8 u64; lane rb owns rows rb+32a
        const int cg = tid >> 5;
        const int c0 = cg * 16;
        const int rb = tid & 31;

        // interleaved real-load L2 prefetch state (tiles t0+2 .. t0+9)
        const float* PF = Bsrc + (long)(t0 + 2) * 128;
        float4 pd[8];
        float pacc = 0.0f;

        u64 r2[4][8];
#pragma unroll
        for (int a = 0; a < 4; a++) {
            const int i = rb + 32 * a;
            const float2* gp = (const float2*)(Gc + i * 128 + c0);
#pragma unroll
            for (int c = 0; c < 8; c++) {
                float2 v = gp[c];
                r2[a][c] = pack2(v.x, v.y);
            }
        }

        for (int k = 0; k < 128; k++) {
            const int p = k & 1, kl = k & 31, kh = k >> 5;
            const int kw = k >> 4;            // warp owning column k
            const int tu = (k & 15) >> 1;     // u64 index of col k in owner
            const int half = k & 1;
            // publish pivot row (unnormalized): each warp its 8-u64 chunk
            if (rb == kl) {
#pragma unroll
                for (int a = 0; a < 4; a++) if (a == kh) {
#pragma unroll
                    for (int c = 0; c < 8; c++) rowk2[p][cg * 8 + c] = r2[a][c];
                }
            }
            // publish pivot column (owning warp, static-index extract)
            if (cg == kw) {
#pragma unroll
                for (int t = 0; t < 8; t++) if (t == tu) {
#pragma unroll
                    for (int a = 0; a < 4; a++) {
                        float lo, hi;
                        unpack2(lo, hi, r2[a][t]);
                        colk[p][rb + 32 * a] = half ? hi : lo;
                    }
                }
            }
            __syncthreads();

            // ---- interleaved L2 prefetch: batch of 8 float4 every 8 pivots.
            // Previous batch consumed here (issued ~8 iterations ago -> ready).
            if ((k & 7) == 0) {
                const int b = k >> 3;              // 0..15
                if (b > 0) {
#pragma unroll
                    for (int i = 0; i < 8; i++)
                        pacc += pd[i].x + pd[i].y + pd[i].z + pd[i].w;
                }
#pragma unroll
                for (int i = 0; i < 8; i++) {
                    const int lidx = b * 8 + i;            // 0..127
                    const int e = (lidx & 15) * 256 + tid; // float4 id in tile
                    const float4* p4 = (const float4*)(PF + (long)(lidx >> 4) * 128
                                                          + (long)(e >> 5) * Ms
                                                          + (e & 31) * 4);
                    pd[i] = __ldcg(p4);
                }
            }

            const float rinv = 1.0f / colk[p][k];
            u64 rk[8];
#pragma unroll
            for (int c = 0; c < 8; c++) rk[c] = rowk2[p][cg * 8 + c];
            const u64 rinv2 = dup2(rinv);
#pragma unroll
            for (int a = 0; a < 4; a++) {
                const int i = rb + 32 * a;
                float fixv;
                if (i == k) {
#pragma unroll
                    for (int c = 0; c < 8; c++) r2[a][c] = mul2(r2[a][c], rinv2);
                    fixv = rinv;
                } else {
                    const float m = -colk[p][i] * rinv;
                    const u64 m2 = dup2(m);
#pragma unroll
                    for (int c = 0; c < 8; c++) ffma2(r2[a][c], rk[c], m2);
                    fixv = m;
                }
                // column-k fixup (owning warp only; static reg index)
                if (cg == kw) {
#pragma unroll
                    for (int t = 0; t < 8; t++) if (t == tu) {
                        float lo, hi;
                        unpack2(lo, hi, r2[a][t]);
                        if (half) hi = fixv; else lo = fixv;
                        r2[a][t] = pack2(lo, hi);
                    }
                }
            }
        }

        // consume last prefetch batch; dead-store (colk dead after GJ;
        // identical-value (0.0f) cross-thread writes are benign)
#pragma unroll
        for (int i = 0; i < 8; i++)
            pacc += pd[i].x + pd[i].y + pd[i].z + pd[i].w;
        colk[0][tid & 127] = pacc * 0.0f;

        // write tf32 A image (A[m][k] = inv[m][k]) straight from registers
#pragma unroll
        for (int a = 0; a < 4; a++) {
            const int i = rb + 32 * a;
#pragma unroll
            for (int c = 0; c < 8; c++) {
                float lo, hi;
                unpack2(lo, hi, r2[a][c]);
                const int gc = c0 + 2 * c;
                *(u64*)(smem + SM_A + img_off(i, gc)) =
                    pack2(to_tf32(lo), to_tf32(hi));
            }
        }
    } else {
        // vn: A = g^T  (A[m][k] = g[k*128+m])
        for (int e = tid; e < 16384; e += 256) {
            const int m = e & 127, k = e >> 7;
            *(float*)(smem + SM_A + img_off(m, k)) = to_tf32(Gc[k * 128 + m]);
        }
    }
    // A-image visibility for all warps is ordered by the barrier inside the
    // first loop iteration below.

    const int wm = (wid & 1) * 64;       // warp row offset (m), WM=64
    const int wn = (wid >> 1) * 32;      // warp col offset (n), WN=32
    const int gidr = lane >> 2;          // 0..7
    const int gidc = lane & 3;           // 0..3
    const int xr = lane & 7;
    const int hi8 = (lane >> 3) & 1;
    const int q16 = lane >> 4;

    // A ldmatrix per-lane row bases (4 mi-tiles of 16 rows)
    u32 arow[4];
#pragma unroll
    for (int mi = 0; mi < 4; mi++)
        arow[mi] = sb + SM_A + (u32)(wm + mi * 16 + xr + hi8 * 8) * 512;

    // B per-lane chunk bases (4 ni-tiles of 8 cols)
    u32 cb[4];
#pragma unroll
    for (int ni = 0; ni < 4; ni++) {
        const int n = wn + ni * 8 + gidr;
        cb[ni] = (u32)(((((n >> 2) ^ (gidc << 1)) & 31) << 4) + (n & 3) * 4);
    }

    for (int j = 0; j < nt; j++) {
        const int p = j & 1;

        if (j + 1 < nt) asm volatile("cp.async.wait_group 1;" ::: "memory");
        else            asm volatile("cp.async.wait_group 0;" ::: "memory");
        __syncthreads();

        const u32 bB = sb + SM_B + p * 65536;

        float acc[4][4][4];
#pragma unroll
        for (int mi = 0; mi < 4; mi++)
#pragma unroll
            for (int ni = 0; ni < 4; ni++)
#pragma unroll
                for (int x = 0; x < 4; x++) acc[mi][ni][x] = 0.0f;

        // software-pipelined fragment loads: frag[ks+1] issued under MMA[ks]
        u32 av[2][4][4];
        u32 bv[2][4][2];
        {
            const u32 acol = (u32)((q16 ^ xr) << 4);
#pragma unroll
            for (int mi = 0; mi < 4; mi++)
                ldsm_x4(av[0][mi][0], av[0][mi][1], av[0][mi][2], av[0][mi][3],
                        arow[mi] + acol);
            const u32 brow = bB + (u32)gidc * 512;
#pragma unroll
            for (int ni = 0; ni < 4; ni++) {
                bv[0][ni][0] = lds32(brow + cb[ni]);
                bv[0][ni][1] = lds32(brow + 2048 + cb[ni]);
            }
        }
#pragma unroll
        for (int ks = 0; ks < 16; ks++) {
            const int cur = ks & 1, nxt = cur ^ 1;
            if (ks + 1 < 16) {
                const u32 acol = (u32)(((2 * (ks + 1) + q16) ^ xr) << 4);
#pragma unroll
                for (int mi = 0; mi < 4; mi++)
                    ldsm_x4(av[nxt][mi][0], av[nxt][mi][1], av[nxt][mi][2], av[nxt][mi][3],
                            arow[mi] + acol);
                const u32 brow = bB + (u32)(8 * (ks + 1) + gidc) * 512;
#pragma unroll
                for (int ni = 0; ni < 4; ni++) {
                    bv[nxt][ni][0] = lds32(brow + cb[ni]);
                    bv[nxt][ni][1] = lds32(brow + 2048 + cb[ni]);
                }
            }
#pragma unroll
            for (int mi = 0; mi < 4; mi++)
#pragma unroll
                for (int ni = 0; ni < 4; ni++)
                    mma16808(acc[mi][ni], av[cur][mi], bv[cur][ni]);
        }

        // ---- epilogue: direct fp32 STG ----
        const long tcol = (long)(t0 + j) * 128;
#pragma unroll
        for (int mi = 0; mi < 4; mi++) {
            const int r = wm + mi * 16 + gidr;
            float* rp = obase + (long)r * Ms + tcol + wn + gidc * 2;
#pragma unroll
            for (int ni = 0; ni < 4; ni++) {
                *(float2*)(rp + ni * 8)          = make_float2(acc[mi][ni][0], acc[mi][ni][1]);
                *(float2*)(rp + ni * 8 + 8 * Ms) = make_float2(acc[mi][ni][2], acc[mi][ni][3]);
            }
        }

        __syncthreads();                 // all warps done reading buf p
        if (j + 2 < nt) cpissue(t0 + j + 2, p);
    }
}

// ---------------------------------------------------------------------------
// Inputs (metadata order): g0,g1,g2 (128x128), v0,v1,v2 (128x512),
// s0,s1,s2 (128x512x512). Output: [v0', s0', v1', s1', v2', s2'] flattened.
// ---------------------------------------------------------------------------
extern "C" void kernel_launch(void* const* d_in, const int* in_sizes, int n_in,
                              void* d_out, int out_size)
{
    const float* g0 = (const float*)d_in[0];
    const float* g1 = (const float*)d_in[1];
    const float* g2 = (const float*)d_in[2];
    const float* v0 = (const float*)d_in[3];
    const float* v1 = (const float*)d_in[4];
    const float* v2 = (const float*)d_in[5];
    const float* s0 = (const float*)d_in[6];
    const float* s1 = (const float*)d_in[7];
    const float* s2 = (const float*)d_in[8];
    float* out = (float*)d_out;

    cudaFuncSetAttribute(main_kernel, cudaFuncAttributeMaxDynamicSharedMemorySize, SMEM_TOTAL);

    main_kernel<<<148, 256, SMEM_TOTAL>>>(g0, g1, g2, v0, v1, v2, s0, s1, s2, out);
}

// round 15
// speedup vs baseline: 1.0718x; 1.0718x over previous
#include <cuda_runtime.h>
#include <cstdint>

typedef unsigned int u32;
typedef unsigned long long u64;

#define CS (65536L + 33554432L)   // per-component output stride (vn + sn)

// ---------------- helpers ---------------------------------------------------
__device__ __forceinline__ u32 smem_u32(const void* p) {
    u32 a;
    asm("{ .reg .u64 t; cvta.to.shared.u64 t, %1; cvt.u32.u64 %0, t; }" : "=r"(a) : "l"(p));
    return a;
}
__device__ __forceinline__ float to_tf32(float x) {
    float r;
    asm("cvt.rna.tf32.f32 %0, %1;" : "=f"(r) : "f"(x));
    return r;
}
// fast reciprocal: rcp.approx + one Newton step (~0.5 ulp, no CALL subroutine)
__device__ __forceinline__ float rcp_nr(float d) {
    float r;
    asm("rcp.approx.f32 %0, %1;" : "=f"(r) : "f"(d));
    float t = __fmaf_rn(-d, r, 1.0f);
    return __fmaf_rn(r, t, r);
}
__device__ __forceinline__ u32 lds32(u32 a) {
    u32 v;
    asm volatile("ld.shared.b32 %0, [%1];" : "=r"(v) : "r"(a));
    return v;
}
__device__ __forceinline__ void ldsm_x4(u32& r0, u32& r1, u32& r2, u32& r3, u32 addr) {
    asm volatile("ldmatrix.sync.aligned.m8n8.x4.shared.b16 {%0,%1,%2,%3}, [%4];"
                 : "=r"(r0), "=r"(r1), "=r"(r2), "=r"(r3) : "r"(addr));
}
__device__ __forceinline__ void mma16808(float* c, const u32* a, const u32* b) {
    asm volatile("mma.sync.aligned.m16n8k8.row.col.f32.tf32.tf32.f32 "
                 "{%0,%1,%2,%3}, {%4,%5,%6,%7}, {%8,%9}, {%0,%1,%2,%3};"
                 : "+f"(c[0]), "+f"(c[1]), "+f"(c[2]), "+f"(c[3])
                 : "r"(a[0]), "r"(a[1]), "r"(a[2]), "r"(a[3]), "r"(b[0]), "r"(b[1]));
}
__device__ __forceinline__ void cp16(u32 dst, const void* src) {
    asm volatile("cp.async.cg.shared.global [%0], [%1], 16;" :: "r"(dst), "l"(src));
}
// swizzled A image offset: row m, 512 B rows, 16 B chunks XOR (m & 7)
__device__ __forceinline__ u32 img_off(int m, int k) {
    return (u32)(m * 512 + (((k >> 2) ^ (m & 7)) << 4) + (k & 3) * 4);
}
// ---- f32x2 helpers ----
__device__ __forceinline__ u64 pack2(float lo, float hi) {
    u64 r;
    asm("mov.b64 %0, {%1, %2};" : "=l"(r) : "f"(lo), "f"(hi));
    return r;
}
__device__ __forceinline__ void unpack2(float& lo, float& hi, u64 v) {
    asm("mov.b64 {%0, %1}, %2;" : "=f"(lo), "=f"(hi) : "l"(v));
}
__device__ __forceinline__ u64 dup2(float w) {
    u64 r;
    asm("mov.b64 %0, {%1, %1};" : "=l"(r) : "f"(w));
    return r;
}
__device__ __forceinline__ void ffma2(u64& c, u64 a, u64 b) {
    asm("fma.rn.f32x2 %0, %1, %2, %0;" : "+l"(c) : "l"(a), "l"(b));
}
__device__ __forceinline__ u64 mul2(u64 a, u64 b) {
    u64 r;
    asm("mul.rn.f32x2 %0, %1, %2;" : "=l"(r) : "l"(a), "l"(b));
    return r;
}

// ---------------------------------------------------------------------------
// Single fused kernel: 148 persistent CTAs x 256 threads.
//  - CTAs 0-144 (sn): in-CTA 2-pivot block Gauss-Jordan inversion of g
//    (64 barrier steps; rank-2 update per step). Pivot-block reciprocal via
//    rcp.approx + 1 Newton step (no IEEE-div CALL subroutine on the path).
//  - CTAs 145-147 (vn): A = g^T image.
//  - GEMM: tf32 mma.m16n8k8, A via ldmatrix, B streamed raw fp32 with
//    cp.async into native [k][n] swizzled layout, double-buffered tiles,
//    software-pipelined fragment loads.
// ---------------------------------------------------------------------------
#define SM_A 0
#define SM_B 65536                       // 2 stages x 64 KB
#define SMEM_TOTAL (65536 * 3)           // 192 KB dynamic

__global__ void __launch_bounds__(256, 1) main_kernel(
    const float* __restrict__ g0, const float* __restrict__ g1, const float* __restrict__ g2,
    const float* __restrict__ v0, const float* __restrict__ v1, const float* __restrict__ v2,
    const float* __restrict__ s0, const float* __restrict__ s1, const float* __restrict__ s2,
    float* __restrict__ out)
{
    __shared__ u64 rowkA[2][128];     // pivot row k   (packed pairs), ping-pong
    __shared__ u64 rowkB[2][128];     // pivot row k+1 (packed pairs), ping-pong
    __shared__ u64 colk2[2][128];     // column pair (a_ik, a_i,k+1), ping-pong
    extern __shared__ char smem[];
    const u32 sb = smem_u32(smem);
    const int tid = threadIdx.x, wid = tid >> 5, lane = tid & 31;
    const int bid = blockIdx.x;

    int comp, t0, t1;
    bool sn;
    if (bid < 145) {
        sn = true;
        comp = bid % 3;
        const int nC = (comp == 0) ? 49 : 48;
        const int ci = bid / 3;
        t0 = (ci * 2048) / nC;
        t1 = ((ci + 1) * 2048) / nC;
    } else {
        sn = false;
        comp = bid - 145;
        t0 = 0;
        t1 = 4;
    }
    const int nt = t1 - t0;
    const long Ms = sn ? 262144L : 512L;
    const float* Bsrc = sn ? (comp == 0 ? s0 : comp == 1 ? s1 : s2)
                           : (comp == 0 ? v0 : comp == 1 ? v1 : v2);
    const float* Gc = comp == 0 ? g0 : (comp == 1 ? g1 : g2);
    float* obase = out + (long)comp * CS + (sn ? 65536 : 0);

    // ---- cp.async pipeline: issue tile t into buffer p ----
    auto cpissue = [&](int t, int p) {
        const float* src = Bsrc + (long)t * 128;
        const u32 bdst = sb + SM_B + p * 65536;
#pragma unroll
        for (int q = 0; q < 16; q++) {
            const int e = q * 256 + tid;
            const int k = e >> 5, c = e & 31;
            cp16(bdst + k * 512 + ((c ^ ((k & 3) << 1)) << 4),
                 src + (long)k * Ms + c * 4);
        }
        asm volatile("cp.async.commit_group;" ::: "memory");
    };

    // get DRAM going before the A-image phase
    cpissue(t0, 0);
    if (nt > 1) cpissue(t0 + 1, 1);

    if (sn) {
        // L2 prefetch of upcoming tiles: fills the DRAM-idle inversion window
        {
            const int npf = nt < 10 ? nt : 10;
            const int seg = tid >> 1;                 // k-row 0..127
            const int half = (tid & 1) * 256;
            for (int t = 2; t < npf; t++) {
                const char* rp = (const char*)(Bsrc + (long)(t0 + t) * 128 + (long)seg * Ms) + half;
                asm volatile("prefetch.global.L2 [%0];" :: "l"(rp));
                asm volatile("prefetch.global.L2 [%0];" :: "l"(rp + 128));
            }
        }

        // ============ in-CTA 2-pivot block Gauss-Jordan inversion ===========
        const int cg = tid >> 5;          // warp = column chunk (warp-uniform)
        const int c0 = cg * 32;
        const int rb = tid & 31;

        u64 r2[4][16];
#pragma unroll
        for (int a = 0; a < 4; a++) {
            const int i = rb + 32 * a;
            if (c0 < 128) {
                const float2* gp = (const float2*)(Gc + i * 128 + c0);
#pragma unroll
                for (int c = 0; c < 16; c++) {
                    float2 v = gp[c];
                    r2[a][c] = pack2(v.x, v.y);
                }
            } else {
#pragma unroll
                for (int c = 0; c < 16; c++) {
                    const int gc = c0 - 128 + 2 * c;
                    r2[a][c] = pack2(gc == i ? 1.0f : 0.0f, gc + 1 == i ? 1.0f : 0.0f);
                }
            }
        }

        for (int k = 0; k < 128; k += 2) {
            const int p = (k >> 1) & 1, kl = k & 31, kh = k >> 5;
            // publish pivot rows k (lane kl) and k+1 (lane kl+1); block a==kh
            if (rb == kl) {
#pragma unroll
                for (int a = 0; a < 4; a++) if (a == kh) {
#pragma unroll
                    for (int c = 0; c < 16; c++) rowkA[p][c0 / 2 + c] = r2[a][c];
                }
            }
            if (rb == kl + 1) {
#pragma unroll
                for (int a = 0; a < 4; a++) if (a == kh) {
#pragma unroll
                    for (int c = 0; c < 16; c++) rowkB[p][c0 / 2 + c] = r2[a][c];
                }
            }
            // publish column pair (warp kh): one u64 per row, both cols k,k+1
            if (cg == kh) {
                const int t2 = kl >> 1;
#pragma unroll
                for (int t = 0; t < 16; t++) if (t == t2) {
#pragma unroll
                    for (int a = 0; a < 4; a++) colk2[p][rb + 32 * a] = r2[a][t];
                }
            }
            __syncthreads();

            // 2x2 pivot block inverse (all threads, wide parallel path)
            float p00, p01, p10, p11;
            unpack2(p00, p01, rowkA[p][k >> 1]);
            unpack2(p10, p11, rowkB[p][k >> 1]);
            const float rdet = rcp_nr(p00 * p11 - p01 * p10);
            const float i00 =  p11 * rdet, i01 = -p01 * rdet;
            const float i10 = -p10 * rdet, i11 =  p00 * rdet;

            if (c0 + 31 >= k && c0 <= k + 129) {
                u64 rka[16], rkb[16];
#pragma unroll
                for (int c = 0; c < 16; c++) {
                    rka[c] = rowkA[p][c0 / 2 + c];
                    rkb[c] = rowkB[p][c0 / 2 + c];
                }
#pragma unroll
                for (int a = 0; a < 4; a++) {
                    const int i = rb + 32 * a;
                    if (i == k) {
                        const u64 w0 = dup2(i00), w1 = dup2(i01);
#pragma unroll
                        for (int c = 0; c < 16; c++) {
                            u64 t = mul2(rka[c], w0);
                            ffma2(t, rkb[c], w1);
                            r2[a][c] = t;
                        }
                    } else if (i == k + 1) {
                        const u64 w0 = dup2(i10), w1 = dup2(i11);
#pragma unroll
                        for (int c = 0; c < 16; c++) {
                            u64 t = mul2(rka[c], w0);
                            ffma2(t, rkb[c], w1);
                            r2[a][c] = t;
                        }
                    } else {
                        float cka, ckb;
                        unpack2(cka, ckb, colk2[p][i]);
                        const u64 m0 = dup2(-(cka * i00 + ckb * i10));
                        const u64 m1 = dup2(-(cka * i01 + ckb * i11));
#pragma unroll
                        for (int c = 0; c < 16; c++) {
                            ffma2(r2[a][c], rka[c], m0);
                            ffma2(r2[a][c], rkb[c], m1);
                        }
                    }
                }
            }
        }

        // write tf32 A image (A[m][k] = inv[m][k]) straight from registers
        if (cg >= 4) {
#pragma unroll
            for (int a = 0; a < 4; a++) {
                const int i = rb + 32 * a;
#pragma unroll
                for (int c = 0; c < 16; c++) {
                    float lo, hi;
                    unpack2(lo, hi, r2[a][c]);
                    const int gc = c0 - 128 + 2 * c;
                    *(u64*)(smem + SM_A + img_off(i, gc)) =
                        pack2(to_tf32(lo), to_tf32(hi));
                }
            }
        }
    } else {
        // vn: A = g^T  (A[m][k] = g[k*128+m])
        for (int e = tid; e < 16384; e += 256) {
            const int m = e & 127, k = e >> 7;
            *(float*)(smem + SM_A + img_off(m, k)) = to_tf32(Gc[k * 128 + m]);
        }
    }
    // A-image visibility for all warps is ordered by the barrier inside the
    // first loop iteration below.

    const int wm = (wid & 1) * 64;       // warp row offset (m), WM=64
    const int wn = (wid >> 1) * 32;      // warp col offset (n), WN=32
    const int gidr = lane >> 2;          // 0..7
    const int gidc = lane & 3;           // 0..3
    const int xr = lane & 7;
    const int hi8 = (lane >> 3) & 1;
    const int q16 = lane >> 4;

    // A ldmatrix per-lane row bases (4 mi-tiles of 16 rows)
    u32 arow[4];
#pragma unroll
    for (int mi = 0; mi < 4; mi++)
        arow[mi] = sb + SM_A + (u32)(wm + mi * 16 + xr + hi8 * 8) * 512;

    // B per-lane chunk bases (4 ni-tiles of 8 cols)
    u32 cb[4];
#pragma unroll
    for (int ni = 0; ni < 4; ni++) {
        const int n = wn + ni * 8 + gidr;
        cb[ni] = (u32)(((((n >> 2) ^ (gidc << 1)) & 31) << 4) + (n & 3) * 4);
    }

    for (int j = 0; j < nt; j++) {
        const int p = j & 1;

        if (j + 1 < nt) asm volatile("cp.async.wait_group 1;" ::: "memory");
        else            asm volatile("cp.async.wait_group 0;" ::: "memory");
        __syncthreads();

        const u32 bB = sb + SM_B + p * 65536;

        float acc[4][4][4];
#pragma unroll
        for (int mi = 0; mi < 4; mi++)
#pragma unroll
            for (int ni = 0; ni < 4; ni++)
#pragma unroll
                for (int x = 0; x < 4; x++) acc[mi][ni][x] = 0.0f;

        // software-pipelined fragment loads: frag[ks+1] issued under MMA[ks]
        u32 av[2][4][4];
        u32 bv[2][4][2];
        {
            const u32 acol = (u32)((q16 ^ xr) << 4);
#pragma unroll
            for (int mi = 0; mi < 4; mi++)
                ldsm_x4(av[0][mi][0], av[0][mi][1], av[0][mi][2], av[0][mi][3],
                        arow[mi] + acol);
            const u32 brow = bB + (u32)gidc * 512;
#pragma unroll
            for (int ni = 0; ni < 4; ni++) {
                bv[0][ni][0] = lds32(brow + cb[ni]);
                bv[0][ni][1] = lds32(brow + 2048 + cb[ni]);
            }
        }
#pragma unroll
        for (int ks = 0; ks < 16; ks++) {
            const int cur = ks & 1, nxt = cur ^ 1;
            if (ks + 1 < 16) {
                const u32 acol = (u32)(((2 * (ks + 1) + q16) ^ xr) << 4);
#pragma unroll
                for (int mi = 0; mi < 4; mi++)
                    ldsm_x4(av[nxt][mi][0], av[nxt][mi][1], av[nxt][mi][2], av[nxt][mi][3],
                            arow[mi] + acol);
                const u32 brow = bB + (u32)(8 * (ks + 1) + gidc) * 512;
#pragma unroll
                for (int ni = 0; ni < 4; ni++) {
                    bv[nxt][ni][0] = lds32(brow + cb[ni]);
                    bv[nxt][ni][1] = lds32(brow + 2048 + cb[ni]);
                }
            }
#pragma unroll
            for (int mi = 0; mi < 4; mi++)
#pragma unroll
                for (int ni = 0; ni < 4; ni++)
                    mma16808(acc[mi][ni], av[cur][mi], bv[cur][ni]);
        }

        // ---- epilogue: direct fp32 STG ----
        const long tcol = (long)(t0 + j) * 128;
#pragma unroll
        for (int mi = 0; mi < 4; mi++) {
            const int r = wm + mi * 16 + gidr;
            float* rp = obase + (long)r * Ms + tcol + wn + gidc * 2;
#pragma unroll
            for (int ni = 0; ni < 4; ni++) {
                *(float2*)(rp + ni * 8)          = make_float2(acc[mi][ni][0], acc[mi][ni][1]);
                *(float2*)(rp + ni * 8 + 8 * Ms) = make_float2(acc[mi][ni][2], acc[mi][ni][3]);
            }
        }

        __syncthreads();                 // all warps done reading buf p
        if (j + 2 < nt) cpissue(t0 + j + 2, p);
    }
}

// ---------------------------------------------------------------------------
// Inputs (metadata order): g0,g1,g2 (128x128), v0,v1,v2 (128x512),
// s0,s1,s2 (128x512x512). Output: [v0', s0', v1', s1', v2', s2'] flattened.
// ---------------------------------------------------------------------------
extern "C" void kernel_launch(void* const* d_in, const int* in_sizes, int n_in,
                              void* d_out, int out_size)
{
    const float* g0 = (const float*)d_in[0];
    const float* g1 = (const float*)d_in[1];
    const float* g2 = (const float*)d_in[2];
    const float* v0 = (const float*)d_in[3];
    const float* v1 = (const float*)d_in[4];
    const float* v2 = (const float*)d_in[5];
    const float* s0 = (const float*)d_in[6];
    const float* s1 = (const float*)d_in[7];
    const float* s2 = (const float*)d_in[8];
    float* out = (float*)d_out;

    cudaFuncSetAttribute(main_kernel, cudaFuncAttributeMaxDynamicSharedMemorySize, SMEM_TOTAL);

    main_kernel<<<148, 256, SMEM_TOTAL>>>(g0, g1, g2, v0, v1, v2, s0, s1, s2, out);
}